// round 13
// baseline (speedup 1.0000x reference)
#include <cuda_runtime.h>
#include <math.h>
#include <stdint.h>

// ---------------------------------------------------------------------------
// DCRNN encoder, TF32 mma.sync, Chebyshev-collapsed diffusion.
// Round 9: 64x64 warp tiles (1.0 smem loads/mma, -33% smem bytes/flop),
// cp.async staging, tf32 cvt at fragment read (same values as before).
// CTA tile 128x128, 128 threads, 4 warps.
// x1 = S@x ; x2 = (2S^2 - I)@x = M2@x (M2 precomputed fp32).
// Layout [N, B, F]: diffusion = A[512,512] @ X[512,4096].
// ---------------------------------------------------------------------------

namespace {
constexpr int TT = 32, BB = 32, NN = 512, HH = 128, LL = 2;
constexpr long NBH  = (long)NN * BB * HH;       // 2,097,152
constexpr long TNBH = (long)TT * NBH;
constexpr long TNBG = (long)TT * NN * BB * 256;
}

// Scratch
__device__ float g_X0[TNBH];
__device__ float g_Xn[TNBH];
__device__ float g_X1[TNBH];
__device__ float g_X2[TNBH];
__device__ float g_GXg[TNBG];
__device__ float g_GXc[TNBH];
__device__ float g_H0[NBH];
__device__ float g_H1[NBH];
__device__ float g_H2[NBH];
__device__ float g_RH0[NBH];
__device__ float g_RH1[NBH];
__device__ float g_RH2[NBH];
__device__ float g_U[NBH];
__device__ float g_M2[512 * 512];
__device__ float g_WgT[(long)LL * 256 * 768];   // [L][256][768]
__device__ float g_WcT[(long)LL * 128 * 768];   // [L][128][768]

// ---------------------------------------------------------------------------
__device__ __forceinline__ uint32_t tf32u(float x) {
    uint32_t u; asm("cvt.rna.tf32.f32 %0, %1;" : "=r"(u) : "f"(x));
    return u;
}
__device__ __forceinline__ void mma_tf32(float* d, const uint32_t* a, const uint32_t* b) {
    asm volatile(
        "mma.sync.aligned.m16n8k8.row.col.f32.tf32.tf32.f32 "
        "{%0,%1,%2,%3}, {%4,%5,%6,%7}, {%8,%9}, {%0,%1,%2,%3};\n"
        : "+f"(d[0]), "+f"(d[1]), "+f"(d[2]), "+f"(d[3])
        : "r"(a[0]), "r"(a[1]), "r"(a[2]), "r"(a[3]), "r"(b[0]), "r"(b[1]));
}
__device__ __forceinline__ uint32_t smem_u32(const void* p) {
    uint32_t a;
    asm("{ .reg .u64 t; cvta.to.shared.u64 t, %1; cvt.u32.u64 %0, t; }" : "=r"(a) : "l"(p));
    return a;
}
__device__ __forceinline__ void cpa16(uint32_t saddr, const void* g) {
    asm volatile("cp.async.ca.shared.global [%0], [%1], 16;" :: "r"(saddr), "l"(g));
}
#define CPA_COMMIT() asm volatile("cp.async.commit_group;")
#define CPA_WAIT1()  asm volatile("cp.async.wait_group 1;")
#define CPA_WAIT0()  asm volatile("cp.async.wait_group 0;")

// ---------------------------------------------------------------------------
// M2 = 2*S@S - I, fp32
__global__ void sq_k(const float* __restrict__ S, float* __restrict__ M2) {
    __shared__ float As[32][33];
    __shared__ float Bs[32][33];
    int tx = threadIdx.x, ty = threadIdx.y;
    int row = (blockIdx.y << 5) + ty, col = (blockIdx.x << 5) + tx;
    float acc = 0.f;
    for (int k0 = 0; k0 < 512; k0 += 32) {
        As[ty][tx] = S[(long)row * 512 + k0 + tx];
        Bs[ty][tx] = S[(long)(k0 + ty) * 512 + col];
        __syncthreads();
#pragma unroll
        for (int kk = 0; kk < 32; kk++) acc += As[ty][kk] * Bs[kk][tx];
        __syncthreads();
    }
    M2[(long)row * 512 + col] = 2.f * acc - (row == col ? 1.f : 0.f);
}

// transpose inputs [T,B,N,D] -> [T,N,B,D]
__global__ void transpose_in_k(const float4* __restrict__ in, float4* __restrict__ out) {
    long idx = (long)blockIdx.x * blockDim.x + threadIdx.x;
    int d4 = (int)(idx & 31);
    long rr = idx >> 5;
    int b = (int)(rr & 31); rr >>= 5;
    int n = (int)(rr & 511); rr >>= 9;
    int t = (int)rr;
    out[idx] = in[((((long)t * BB + b) * NN + n) << 5) + d4];
}

// transpose hidden [B,N,H] -> [N,B,H]
__global__ void transpose_h_k(const float4* __restrict__ in, float4* __restrict__ out) {
    long idx = (long)blockIdx.x * blockDim.x + threadIdx.x;
    int d4 = (int)(idx & 31);
    int b  = (int)((idx >> 5) & 31);
    int n  = (int)(idx >> 10);
    out[idx] = in[(((long)b * NN + n) << 5) + d4];
}

// all 4 weight transposes in one kernel: W [768,O] -> WT [O,768]
__global__ void transpose_w_all(const float* __restrict__ Wg, const float* __restrict__ Wc,
                                float* __restrict__ WgT, float* __restrict__ WcT) {
    int idx = blockIdx.x * blockDim.x + threadIdx.x;
    const int NG = 2 * 768 * 256;
    const int NCt = 2 * 768 * 128;
    if (idx < NG) {
        int l = idx / (768 * 256), r = idx % (768 * 256);
        int f = r / 256, o = r % 256;
        WgT[(long)l * 256 * 768 + (long)o * 768 + f] = Wg[(long)l * 768 * 256 + (long)f * 256 + o];
    } else if (idx < NG + NCt) {
        int j = idx - NG;
        int l = j / (768 * 128), r = j % (768 * 128);
        int f = r / 128, o = r % 128;
        WcT[(long)l * 128 * 768 + (long)o * 768 + f] = Wc[(long)l * 768 * 128 + (long)f * 128 + o];
    }
}

// ---------------------------------------------------------------------------
// Batched diffusion GEMM (TF32): z = 2*pair + which:
//   C_which[pair] = (which ? M2 : S) @ B[pair]     B: [512, 4096]
// CTA 128x128, 128 threads, 4 warps of 64x64. cp.async double buffer.
__global__ __launch_bounds__(128, 2) void gemm_diff2(
    const float* __restrict__ Sa, const float* __restrict__ M2a,
    const float* __restrict__ Bbase, long bStride,
    float* __restrict__ C1, float* __restrict__ C2, long cStride)
{
    constexpr int NC = 4096;
    const int pair = blockIdx.z >> 1, which = blockIdx.z & 1;
    const float* A  = which ? M2a : Sa;
    const float* Bp = Bbase + (long)pair * bStride;
    float* Cp = (which ? C2 : C1) + (long)pair * cStride;

    __shared__ float As[2][128][20];   // [stage][m][k] pitch 20
    __shared__ float Bs[2][16][136];   // [stage][k][n]
    const uint32_t sA = smem_u32(As), sB = smem_u32(Bs);

    const int tid = threadIdx.x;
    const int lane = tid & 31, warp = tid >> 5;
    const int wm0 = (warp & 1) << 6;       // 0/64
    const int wn0 = (warp >> 1) << 6;      // 0/64
    const int r = lane >> 2, c = lane & 3;
    const int m0 = blockIdx.y << 7, n0 = blockIdx.x << 7;

    const int b_k  = tid >> 3;             // k 0..15
    const int b_n4 = (tid & 7) << 4;       // n 0..112 step 16

    float acc[4][8][4] = {};

    auto copy_tile = [&](int k0, int s) {
        const float* ap = A + (long)(m0 + tid) * 512 + k0;
        uint32_t da = sA + (uint32_t)(((s * 128 + tid) * 20) * 4);
#pragma unroll
        for (int q = 0; q < 16; q += 4) cpa16(da + q * 4, ap + q);
        const float* bp = Bp + (long)(k0 + b_k) * NC + n0 + b_n4;
        uint32_t db = sB + (uint32_t)((((s * 16 + b_k) * 136) + b_n4) * 4);
#pragma unroll
        for (int q = 0; q < 16; q += 4) cpa16(db + q * 4, bp + q);
    };

    copy_tile(0, 0); CPA_COMMIT();
    int cur = 0;
    for (int kt = 0; kt < 32; kt++) {
        const bool more = (kt + 1 < 32);
        if (more) { copy_tile((kt + 1) << 4, cur ^ 1); CPA_COMMIT(); }
        if (more) { CPA_WAIT1(); } else { CPA_WAIT0(); }
        __syncthreads();
#pragma unroll
        for (int kk = 0; kk < 16; kk += 8) {
            uint32_t af[4][4], bf[8][2];
#pragma unroll
            for (int mi = 0; mi < 4; mi++) {
                int mm = wm0 + mi * 16 + r;
                af[mi][0] = tf32u(As[cur][mm][kk + c]);
                af[mi][1] = tf32u(As[cur][mm + 8][kk + c]);
                af[mi][2] = tf32u(As[cur][mm][kk + c + 4]);
                af[mi][3] = tf32u(As[cur][mm + 8][kk + c + 4]);
            }
#pragma unroll
            for (int ni = 0; ni < 8; ni++) {
                int nn = wn0 + ni * 8 + r;
                bf[ni][0] = tf32u(Bs[cur][kk + c][nn]);
                bf[ni][1] = tf32u(Bs[cur][kk + c + 4][nn]);
            }
#pragma unroll
            for (int mi = 0; mi < 4; mi++)
#pragma unroll
                for (int ni = 0; ni < 8; ni++)
                    mma_tf32(acc[mi][ni], af[mi], bf[ni]);
        }
        __syncthreads();
        cur ^= 1;
    }
#pragma unroll
    for (int mi = 0; mi < 4; mi++) {
        int row = m0 + wm0 + mi * 16 + r;
#pragma unroll
        for (int ni = 0; ni < 8; ni++) {
            int col = n0 + wn0 + ni * 8 + 2 * c;
            const float* ap = acc[mi][ni];
            long o0 = (long)row * NC + col, o1 = o0 + 8L * NC;
            float2 q0, q1;
            q0.x = ap[0]; q0.y = ap[1]; q1.x = ap[2]; q1.y = ap[3];
            *(float2*)(Cp + o0) = q0;
            *(float2*)(Cp + o1) = q1;
        }
    }
}

// ---------------------------------------------------------------------------
// Projection GEMM (TF32): D = f( sum_seg A_seg @ WT_seg^T + pre + bias )
// A segs: [M,128]. WT: [O,768] row-major; seg s uses cols s*256+xh_off+0..127.
// W tile staged [n][k] pitch 20 (layout-matched to gmem rows).
// modes: 0 plain(+bias)->outC; 1 gates; 2 candidate + GRU update + scatter.
__global__ __launch_bounds__(128, 2) void gemm_proj_t(
    const float* __restrict__ A0, const float* __restrict__ A1, const float* __restrict__ A2,
    const float* __restrict__ WT, int xh_off, int nout,
    const float* __restrict__ pre, const float* __restrict__ bias,
    float* __restrict__ outC, int mode,
    const float* __restrict__ h0c, float* __restrict__ rh0, float* __restrict__ uarr,
    float* __restrict__ h0w, float* __restrict__ out_nbh, float* __restrict__ out_bnh,
    float* __restrict__ finp, int t)
{
    __shared__ float As[2][128][20];   // [stage][m][k]
    __shared__ float Ws[2][128][20];   // [stage][n][k]
    const uint32_t sA = smem_u32(As), sW = smem_u32(Ws);

    const int tid = threadIdx.x;
    const int lane = tid & 31, warp = tid >> 5;
    const int wm0 = (warp & 1) << 6;
    const int wn0 = (warp >> 1) << 6;
    const int r = lane >> 2, c = lane & 3;
    const int m0 = blockIdx.y << 7, n0 = blockIdx.x << 7;

    const float* Aseg[3] = {A0, A1, A2};

    float acc[4][8][4] = {};

    auto copy_tile = [&](int kt, int s) {
        int seg = kt >> 3, within = (kt & 7) << 4;
        const float* ap = Aseg[seg] + (long)(m0 + tid) * 128 + within;
        uint32_t da = sA + (uint32_t)(((s * 128 + tid) * 20) * 4);
#pragma unroll
        for (int q = 0; q < 16; q += 4) cpa16(da + q * 4, ap + q);
        const float* wp = WT + (long)(n0 + tid) * 768 + seg * 256 + xh_off + within;
        uint32_t dw = sW + (uint32_t)(((s * 128 + tid) * 20) * 4);
#pragma unroll
        for (int q = 0; q < 16; q += 4) cpa16(dw + q * 4, wp + q);
    };

    copy_tile(0, 0); CPA_COMMIT();
    int cur = 0;
    for (int kt = 0; kt < 24; kt++) {
        const bool more = (kt + 1 < 24);
        if (more) { copy_tile(kt + 1, cur ^ 1); CPA_COMMIT(); }
        if (more) { CPA_WAIT1(); } else { CPA_WAIT0(); }
        __syncthreads();
#pragma unroll
        for (int kk = 0; kk < 16; kk += 8) {
            uint32_t af[4][4], bf[8][2];
#pragma unroll
            for (int mi = 0; mi < 4; mi++) {
                int mm = wm0 + mi * 16 + r;
                af[mi][0] = tf32u(As[cur][mm][kk + c]);
                af[mi][1] = tf32u(As[cur][mm + 8][kk + c]);
                af[mi][2] = tf32u(As[cur][mm][kk + c + 4]);
                af[mi][3] = tf32u(As[cur][mm + 8][kk + c + 4]);
            }
#pragma unroll
            for (int ni = 0; ni < 8; ni++) {
                int nn = wn0 + ni * 8 + r;
                bf[ni][0] = tf32u(Ws[cur][nn][kk + c]);
                bf[ni][1] = tf32u(Ws[cur][nn][kk + c + 4]);
            }
#pragma unroll
            for (int mi = 0; mi < 4; mi++)
#pragma unroll
                for (int ni = 0; ni < 8; ni++)
                    mma_tf32(acc[mi][ni], af[mi], bf[ni]);
        }
        __syncthreads();
        cur ^= 1;
    }

#pragma unroll
    for (int mi = 0; mi < 4; mi++) {
#pragma unroll
        for (int ni = 0; ni < 8; ni++) {
            const float* ap = acc[mi][ni];
#pragma unroll
            for (int half = 0; half < 2; half++) {
                int row = m0 + wm0 + mi * 16 + r + half * 8;
                float v0 = ap[half * 2 + 0];
                float v1 = ap[half * 2 + 1];
                int col = n0 + wn0 + ni * 8 + 2 * c;
                if (mode == 0) {
                    if (bias) { v0 += bias[col]; v1 += bias[col + 1]; }
                    float2 o; o.x = v0; o.y = v1;
                    *(float2*)(outC + (long)row * nout + col) = o;
                } else if (mode == 1) {
                    const float* pp = pre + (long)row * 256 + col;
                    v0 += pp[0]; v1 += pp[1];
                    float g0 = 1.f / (1.f + __expf(-v0));
                    float g1 = 1.f / (1.f + __expf(-v1));
                    if (col < 128) {
                        long o = (long)row * 128 + col;
                        float2 h = *(const float2*)(h0c + o);
                        float2 out; out.x = g0 * h.x; out.y = g1 * h.y;
                        *(float2*)(rh0 + o) = out;
                    } else {
                        long o = (long)row * 128 + (col - 128);
                        float2 out; out.x = g0; out.y = g1;
                        *(float2*)(uarr + o) = out;
                    }
                } else {
                    long o = (long)row * 128 + col;
                    const float* pp = pre + o;
                    v0 += pp[0]; v1 += pp[1];
                    float c0 = tanhf(v0), c1 = tanhf(v1);
                    float2 uu = *(const float2*)(uarr + o);
                    float2 hh = *(const float2*)(h0c + o);
                    float hn0 = uu.x * hh.x + (1.f - uu.x) * c0;
                    float hn1 = uu.y * hh.y + (1.f - uu.y) * c1;
                    float2 out; out.x = hn0; out.y = hn1;
                    *(float2*)(h0w + o) = out;
                    if (out_nbh) *(float2*)(out_nbh + o) = out;
                    int nn2 = row >> 5, bb2 = row & 31;
                    if (out_bnh)
                        *(float2*)(out_bnh + ((((long)t * BB + bb2) * NN + nn2) * HH + col)) = out;
                    if (finp)
                        *(float2*)(finp + (((long)bb2 * NN + nn2) * HH + col)) = out;
                }
            }
        }
    }
}

// ---------------------------------------------------------------------------
extern "C" void kernel_launch(void* const* d_in, const int* in_sizes, int n_in,
                              void* d_out, int out_size) {
    (void)in_sizes; (void)n_in; (void)out_size;
    const float* inputs = (const float*)d_in[0];
    const float* ih     = (const float*)d_in[1];
    const float* S      = (const float*)d_in[2];
    const float* Wg     = (const float*)d_in[3];
    const float* bg     = (const float*)d_in[4];
    const float* Wc     = (const float*)d_in[5];
    const float* bc     = (const float*)d_in[6];
    float* fin    = (float*)d_out;
    float* outcur = fin + (long)LL * BB * NN * HH;

    float *pX0, *pXn, *pX1, *pX2, *pGXg, *pGXc;
    float *pH0, *pH1, *pH2, *pRH0, *pRH1, *pRH2, *pU, *pM2, *pWgT, *pWcT;
    cudaGetSymbolAddress((void**)&pX0, g_X0);
    cudaGetSymbolAddress((void**)&pXn, g_Xn);
    cudaGetSymbolAddress((void**)&pX1, g_X1);
    cudaGetSymbolAddress((void**)&pX2, g_X2);
    cudaGetSymbolAddress((void**)&pGXg, g_GXg);
    cudaGetSymbolAddress((void**)&pGXc, g_GXc);
    cudaGetSymbolAddress((void**)&pH0, g_H0);
    cudaGetSymbolAddress((void**)&pH1, g_H1);
    cudaGetSymbolAddress((void**)&pH2, g_H2);
    cudaGetSymbolAddress((void**)&pRH0, g_RH0);
    cudaGetSymbolAddress((void**)&pRH1, g_RH1);
    cudaGetSymbolAddress((void**)&pRH2, g_RH2);
    cudaGetSymbolAddress((void**)&pU, g_U);
    cudaGetSymbolAddress((void**)&pM2, g_M2);
    cudaGetSymbolAddress((void**)&pWgT, g_WgT);
    cudaGetSymbolAddress((void**)&pWcT, g_WcT);

    // One-time prep
    sq_k<<<dim3(16, 16), dim3(32, 32)>>>(S, pM2);
    transpose_in_k<<<65536, 256>>>((const float4*)inputs, (float4*)pX0);
    transpose_w_all<<<2304, 256>>>(Wg, Wc, pWgT, pWcT);

    for (int l = 0; l < LL; l++) {
        const float* Xin = (l == 0) ? pX0 : pXn;
        const float* wgt = pWgT + (long)l * 256 * 768;
        const float* wct = pWcT + (long)l * 128 * 768;

        // --- parallel precompute of x-contributions (all T, both diffusion terms) ---
        gemm_diff2<<<dim3(32, 4, 2 * TT), 128>>>(S, pM2, Xin, NBH, pX1, pX2, NBH);
        gemm_proj_t<<<dim3(2, 4096), 128>>>(Xin, pX1, pX2, wgt, 0, 256,
            nullptr, bg + l * 256, pGXg, 0,
            nullptr, nullptr, nullptr, nullptr, nullptr, nullptr, nullptr, 0);
        gemm_proj_t<<<dim3(1, 4096), 128>>>(Xin, pX1, pX2, wct, 0, 128,
            nullptr, bc + l * 128, pGXc, 0,
            nullptr, nullptr, nullptr, nullptr, nullptr, nullptr, nullptr, 0);

        transpose_h_k<<<2048, 256>>>((const float4*)(ih + (long)l * BB * NN * HH), (float4*)pH0);

        // --- sequential recurrence: 4 dependent kernels per step ---
        for (int t = 0; t < TT; t++) {
            gemm_diff2<<<dim3(32, 4, 2), 128>>>(S, pM2, pH0, 0, pH1, pH2, 0);
            gemm_proj_t<<<dim3(2, 128), 128>>>(pH0, pH1, pH2, wgt, 128, 256,
                pGXg + (long)t * NN * BB * 256, nullptr, nullptr, 1,
                pH0, pRH0, pU, nullptr, nullptr, nullptr, nullptr, 0);
            gemm_diff2<<<dim3(32, 4, 2), 128>>>(S, pM2, pRH0, 0, pRH1, pRH2, 0);
            gemm_proj_t<<<dim3(1, 128), 128>>>(pRH0, pRH1, pRH2, wct, 128, 128,
                pGXc + (long)t * NN * BB * 128, nullptr, nullptr, 2,
                pH0, nullptr, pU, pH0,
                (l == 0) ? (pXn + (long)t * NBH) : nullptr,
                (l == 1) ? outcur : nullptr,
                (t == TT - 1) ? (fin + (long)l * BB * NN * HH) : nullptr, t);
        }
    }
}